// round 14
// baseline (speedup 1.0000x reference)
#include <cuda_runtime.h>
#include <math.h>
#include <stdint.h>

#define Bsz 16384
#define Hd  1024
#define Cc  2
#define PPCc 24
#define Pp  48
#define EPSf 1e-4f

#define DIST_BLOCKS (Bsz / 64)          // 256
#define UALL_BLOCKS 64                  // 4 j-chunks x 16 i-splits, 48 accs

// bf16 smem tiles: rows of 16 bf16x2 words, stride 18 (even => 8B stores ok)
#define XROW_STRIDE 18
#define XBUF_WORDS (64 * XROW_STRIDE)   // 1152
#define PBUF_WORDS (48 * XROW_STRIDE)   // 864
#define SMEM_WORDS (2 * XBUF_WORDS + 2 * PBUF_WORDS)   // 4032 words = 16128 B

// Output layout (concatenated reference tuple, all fp32):
//   pos [B,1] | shared [B,H] | logits [B,C] | distance [B,P]
#define POS_OFF    ((size_t)0)
#define SHARED_OFF ((size_t)Bsz)
#define LOGITS_OFF (SHARED_OFF + (size_t)Bsz * Hd)
#define DIST_OFF   (LOGITS_OFF + (size_t)Bsz * Cc)

// Single scratch symbol -> ONE memset node per replay.
__device__ float g_scratch[Pp * Hd + Pp];
#define G_UALL   (g_scratch)
#define G_SIMSUM (g_scratch + Pp * Hd)

__device__ __forceinline__ uint32_t bf2(float lo, float hi) {
    uint32_t r;
    asm("cvt.rn.bf16x2.f32 %0, %1, %2;" : "=r"(r) : "f"(hi), "f"(lo));
    return r;
}

// ---------------------------------------------------------------------------
// K2 fused single launch:
//   blocks [0, DIST_BLOCKS):  bf16 distance GEMM (m16n8k16, double-buffered
//                             register staging with fp32->bf16 convert;
//                             exact fp32 norms from the loader)
//   blocks [DIST_BLOCKS, ..): u_all blocks (exact fp32)
// ---------------------------------------------------------------------------
__global__ __launch_bounds__(256, 3) void k2_fused(
    const float* __restrict__ x, const float* __restrict__ protos,
    const float* __restrict__ llw, const float* __restrict__ W,
    float* __restrict__ out) {
    __shared__ uint32_t smem_raw[SMEM_WORDS];   // 16128 B

    const int tid = threadIdx.x;

    // ======================= role: u_all =======================
    if (blockIdx.x >= DIST_BLOCKS) {
        float* psh = (float*)smem_raw;          // 48*64 floats = 12 KB
        const int b  = blockIdx.x - DIST_BLOCKS;
        const int j0 = (b & 3) * 256;
        const int i0 = (b >> 2) * 64;           // 16 i-splits
        for (int idx = tid; idx < Pp * 64; idx += 256) {
            const int p = idx >> 6, i = idx & 63;
            psh[idx] = protos[(size_t)p * Hd + i0 + i];
        }
        __syncthreads();
        const int j = j0 + tid;
        float acc[Pp];
#pragma unroll
        for (int p = 0; p < Pp; p++) acc[p] = 0.f;
        const float* Wp = W + (size_t)i0 * Hd + j;
#pragma unroll 2
        for (int i = 0; i < 64; i += 8) {
            float w[8];
#pragma unroll
            for (int q = 0; q < 8; q++) w[q] = __ldcs(Wp + (size_t)(i + q) * Hd);
#pragma unroll
            for (int p = 0; p < Pp; p++) {
                float a = acc[p];
#pragma unroll
                for (int q = 0; q < 8; q++) a = fmaf(w[q], psh[p * 64 + i + q], a);
                acc[p] = a;
            }
        }
#pragma unroll
        for (int p = 0; p < Pp; p++)
            atomicAdd(&G_UALL[p * Hd + j], acc[p]);
        return;
    }

    // ======================= role: distance GEMM =======================
    uint32_t* XBUF0 = smem_raw;
    uint32_t* XBUF1 = smem_raw + XBUF_WORDS;
    uint32_t* PBUF0 = smem_raw + 2 * XBUF_WORDS;
    uint32_t* PBUF1 = smem_raw + 2 * XBUF_WORDS + PBUF_WORDS;

    const int lane = tid & 31, warp = tid >> 5;
    const int row0 = blockIdx.x * 64;
    const int g  = lane >> 2;
    const int t4 = lane & 3;

    const int xrow = tid >> 3;                 // 0..31 (rows xrow, xrow+32)
    const int xk4  = (tid & 7) << 2;           // float offset in 32-K tile
    const int xwrd = (tid & 7) << 1;           // bf16x2 word offset
    const float* xbase  = x + (size_t)(row0 + xrow) * Hd + xk4;
    const float* pbase0 = protos + (size_t)xrow * Hd + xk4;
    const float* pbase1 = protos + (size_t)(xrow + 32) * Hd + xk4;
    const bool   phas1  = (tid < 128);         // proto rows 32..47

    float4 xc0 = __ldcs((const float4*)xbase);
    float4 xc1 = __ldcs((const float4*)(xbase + (size_t)32 * Hd));
    float4 pc0 = __ldg((const float4*)pbase0);
    float4 pc1 = phas1 ? __ldg((const float4*)pbase1) : make_float4(0.f, 0.f, 0.f, 0.f);

    float acc[3][4];
#pragma unroll
    for (int n = 0; n < 3; n++)
#pragma unroll
        for (int q = 0; q < 4; q++) acc[n][q] = 0.f;
    float sq0 = 0.f, sq1 = 0.f, pq0 = 0.f, pq1 = 0.f;

    const int Rg    = (warp & 3) * 16 + g;     // A rows Rg, Rg+8
    const int nhalf = warp >> 2;

    for (int s = 0; s < 32; s++) {
        uint32_t* xd = (s & 1) ? XBUF1 : XBUF0;
        uint32_t* pd = (s & 1) ? PBUF1 : PBUF0;

        // ---- stage tile s: exact fp32 norms + bf16 convert + STS ----
        sq0 = fmaf(xc0.x, xc0.x, sq0); sq0 = fmaf(xc0.y, xc0.y, sq0);
        sq0 = fmaf(xc0.z, xc0.z, sq0); sq0 = fmaf(xc0.w, xc0.w, sq0);
        sq1 = fmaf(xc1.x, xc1.x, sq1); sq1 = fmaf(xc1.y, xc1.y, sq1);
        sq1 = fmaf(xc1.z, xc1.z, sq1); sq1 = fmaf(xc1.w, xc1.w, sq1);
        pq0 = fmaf(pc0.x, pc0.x, pq0); pq0 = fmaf(pc0.y, pc0.y, pq0);
        pq0 = fmaf(pc0.z, pc0.z, pq0); pq0 = fmaf(pc0.w, pc0.w, pq0);
        {
            uint2 v;
            v.x = bf2(xc0.x, xc0.y); v.y = bf2(xc0.z, xc0.w);
            *(uint2*)&xd[xrow * XROW_STRIDE + xwrd] = v;
            v.x = bf2(xc1.x, xc1.y); v.y = bf2(xc1.z, xc1.w);
            *(uint2*)&xd[(xrow + 32) * XROW_STRIDE + xwrd] = v;
            v.x = bf2(pc0.x, pc0.y); v.y = bf2(pc0.z, pc0.w);
            *(uint2*)&pd[xrow * XROW_STRIDE + xwrd] = v;
            if (phas1) {
                pq1 = fmaf(pc1.x, pc1.x, pq1); pq1 = fmaf(pc1.y, pc1.y, pq1);
                pq1 = fmaf(pc1.z, pc1.z, pq1); pq1 = fmaf(pc1.w, pc1.w, pq1);
                v.x = bf2(pc1.x, pc1.y); v.y = bf2(pc1.z, pc1.w);
                *(uint2*)&pd[(xrow + 32) * XROW_STRIDE + xwrd] = v;
            }
        }
        __syncthreads();

        // ---- prefetch tile s+1 (latency hidden under mma phase) ----
        if (s < 31) {
            const int ko = (s + 1) * 32;
            xc0 = __ldcs((const float4*)(xbase + ko));
            xc1 = __ldcs((const float4*)(xbase + (size_t)32 * Hd + ko));
            pc0 = __ldg((const float4*)(pbase0 + ko));
            if (phas1) pc1 = __ldg((const float4*)(pbase1 + ko));
        }

        // ---- mma over buf: 2 k-chunks of 16 x 3 n-tiles ----
#pragma unroll
        for (int kc2 = 0; kc2 < 16; kc2 += 8) {      // word offset of k-chunk
            const uint32_t a0 = xd[(Rg    ) * XROW_STRIDE + kc2 + t4];
            const uint32_t a1 = xd[(Rg + 8) * XROW_STRIDE + kc2 + t4];
            const uint32_t a2 = xd[(Rg    ) * XROW_STRIDE + kc2 + t4 + 4];
            const uint32_t a3 = xd[(Rg + 8) * XROW_STRIDE + kc2 + t4 + 4];
#pragma unroll
            for (int nt = 0; nt < 3; nt++) {
                const int prow = (nhalf * 3 + nt) * 8 + g;
                const uint32_t b0 = pd[prow * XROW_STRIDE + kc2 + t4];
                const uint32_t b1 = pd[prow * XROW_STRIDE + kc2 + t4 + 4];
                asm volatile(
                    "mma.sync.aligned.m16n8k16.row.col.f32.bf16.bf16.f32 "
                    "{%0,%1,%2,%3}, {%4,%5,%6,%7}, {%8,%9}, {%0,%1,%2,%3};"
                    : "+f"(acc[nt][0]), "+f"(acc[nt][1]),
                      "+f"(acc[nt][2]), "+f"(acc[nt][3])
                    : "r"(a0), "r"(a1), "r"(a2), "r"(a3), "r"(b0), "r"(b1));
            }
        }
    }
    __syncthreads();   // all mma done; safe to alias smem as epilogue scratch

    // aliased epilogue scratch
    float* ext     = (float*)smem_raw;
    float* x2s     = ext;          // 64
    float* p2s     = ext + 64;     // 48
    float* logit_s = ext + 112;    // 128
    float* simPart = ext + 240;    // 48
    float* wks     = ext + 288;    // 96
    for (int i = tid; i < 384; i += 256)
        ext[i] = (i < 288) ? 0.f : llw[i - 288];
    __syncthreads();

    // loader-based exact fp32 norms (8 partials per row)
    atomicAdd(&x2s[xrow],      sq0);
    atomicAdd(&x2s[xrow + 32], sq1);
    atomicAdd(&p2s[xrow],      pq0);
    if (phas1) atomicAdd(&p2s[xrow + 32], pq1);
    __syncthreads();

    const int ra = Rg, rb = Rg + 8;
    const float x2a = x2s[ra], x2b = x2s[rb];
    float lgA0 = 0.f, lgA1 = 0.f, lgB0 = 0.f, lgB1 = 0.f;
    float* dd = out + DIST_OFF + (size_t)row0 * 48;
#pragma unroll
    for (int nt = 0; nt < 3; nt++) {
        const int c0 = (nhalf * 3 + nt) * 8 + t4 * 2, c1 = c0 + 1;
        const float dA0 = fmaf(-2.f, acc[nt][0], x2a + p2s[c0]);
        const float dA1 = fmaf(-2.f, acc[nt][1], x2a + p2s[c1]);
        const float dB0 = fmaf(-2.f, acc[nt][2], x2b + p2s[c0]);
        const float dB1 = fmaf(-2.f, acc[nt][3], x2b + p2s[c1]);
        __stcs((float2*)(dd + (size_t)ra * 48 + c0), make_float2(dA0, dA1));
        __stcs((float2*)(dd + (size_t)rb * 48 + c0), make_float2(dB0, dB1));
        const float sA0 = logf((dA0 + 1.f) / (dA0 + EPSf));
        const float sA1 = logf((dA1 + 1.f) / (dA1 + EPSf));
        const float sB0 = logf((dB0 + 1.f) / (dB0 + EPSf));
        const float sB1 = logf((dB1 + 1.f) / (dB1 + EPSf));
        lgA0 = fmaf(sA0, wks[c0], lgA0); lgA0 = fmaf(sA1, wks[c1], lgA0);
        lgA1 = fmaf(sA0, wks[48 + c0], lgA1); lgA1 = fmaf(sA1, wks[48 + c1], lgA1);
        lgB0 = fmaf(sB0, wks[c0], lgB0); lgB0 = fmaf(sB1, wks[c1], lgB0);
        lgB1 = fmaf(sB0, wks[48 + c0], lgB1); lgB1 = fmaf(sB1, wks[48 + c1], lgB1);
        atomicAdd(&simPart[c0], sA0 + sB0);
        atomicAdd(&simPart[c1], sA1 + sB1);
    }
    atomicAdd(&logit_s[ra * 2 + 0], lgA0);
    atomicAdd(&logit_s[ra * 2 + 1], lgA1);
    atomicAdd(&logit_s[rb * 2 + 0], lgB0);
    atomicAdd(&logit_s[rb * 2 + 1], lgB1);
    __syncthreads();

    if (tid < 128) out[LOGITS_OFF + (size_t)row0 * 2 + tid] = logit_s[tid];
    if (tid < 48)  atomicAdd(&G_SIMSUM[tid], simPart[tid]);
}

// ---------------------------------------------------------------------------
// K3: in-block argmax -> u[jstar] to smem -> fused shared copy-out + pos dot.
// ---------------------------------------------------------------------------
__global__ __launch_bounds__(512) void k3_pos(
    const float* __restrict__ shr, const float* __restrict__ bb,
    const int* __restrict__ flag, float* __restrict__ out) {
    __shared__ float us[Hd];
    __shared__ int   js_s;
    const int tid = threadIdx.x;

    if (tid < 32) {
        const int idx = (flag[0] != 0) ? 1 : 0;
        float v = (tid < PPCc) ? G_SIMSUM[idx * PPCc + tid] : -INFINITY;
        int bj = tid;
        for (int o = 16; o; o >>= 1) {
            const float ov = __shfl_xor_sync(0xffffffffu, v, o);
            const int   oj = __shfl_xor_sync(0xffffffffu, bj, o);
            if (ov > v || (ov == v && oj < bj)) { v = ov; bj = oj; }
        }
        if (tid == 0) js_s = idx * PPCc + bj;
    }
    __syncthreads();
    const int js = js_s;
    for (int i = tid; i < Hd; i += 512) us[i] = G_UALL[js * Hd + i];
    __syncthreads();

    const int warp = tid >> 5, lane = tid & 31;
    const int r = blockIdx.x * 16 + warp;
    const float4* src = (const float4*)(shr + (size_t)r * Hd);
    float4*       dst = (float4*)(out + SHARED_OFF + (size_t)r * Hd);
    const float4* uf  = (const float4*)us;
    float a0 = 0.f, a1 = 0.f, a2 = 0.f, a3 = 0.f;
#pragma unroll
    for (int t = lane; t < Hd / 4; t += 32) {
        const float4 v = __ldcs(src + t);
        __stcs(dst + t, v);
        const float4 u4 = uf[t];
        a0 = fmaf(v.x, u4.x, a0);
        a1 = fmaf(v.y, u4.y, a1);
        a2 = fmaf(v.z, u4.z, a2);
        a3 = fmaf(v.w, u4.w, a3);
    }
    float acc = (a0 + a1) + (a2 + a3);
    for (int o = 16; o; o >>= 1) acc += __shfl_xor_sync(0xffffffffu, acc, o);
    if (lane == 0) out[POS_OFF + r] = acc + __ldg(bb);
}

// ---------------------------------------------------------------------------
extern "C" void kernel_launch(void* const* d_in, const int* in_sizes, int n_in,
                              void* d_out, int out_size) {
    const float* x      = (const float*)d_in[0];  // specific_user [B,H]
    const float* shr    = (const float*)d_in[1];  // shared_user   [B,H]
    const float* protos = (const float*)d_in[2];  // [P,H]
    const float* llw    = (const float*)d_in[3];  // [C,P]
    const float* W      = (const float*)d_in[4];  // [1,H,H]
    const float* bb     = (const float*)d_in[5];  // [1]
    const int*   flag   = (const int*)d_in[6];    // scalar
    float* out = (float*)d_out;

    // single memset node (uall + simSum live in one symbol)
    void* scr_ptr = nullptr;
    cudaGetSymbolAddress(&scr_ptr, g_scratch);
    cudaMemsetAsync(scr_ptr, 0, (size_t)(Pp * Hd + Pp) * sizeof(float));

    k2_fused<<<DIST_BLOCKS + UALL_BLOCKS, 256>>>(x, protos, llw, W, out);
    k3_pos  <<<Bsz / 16, 512>>>(shr, bb, flag, out);
}

// round 16
// speedup vs baseline: 1.1028x; 1.1028x over previous
#include <cuda_runtime.h>
#include <math.h>
#include <stdint.h>

#define Bsz 16384
#define Hd  1024
#define Cc  2
#define PPCc 24
#define Pp  48
#define EPSf 1e-4f

#define DIST_BLOCKS (Bsz / 64)          // 256 (64-row tiles)
#define UALL_BLOCKS 128                 // 4 j-chunks x 16 i-splits x 2 halves

// 64-wide K stages, raw fp32 in smem. Row stride 68 floats (68 mod 32 = 4
// => the 8 fragment rows per warp land on distinct banks; 272B keeps 16B align)
#define KSTEP 64
#define ROW_STRIDE 68
#define B_FLOAT_OFF (64 * ROW_STRIDE)           // B tile after 64 A rows
#define STAGE_FLOATS ((64 + 48) * ROW_STRIDE)   // 7616
#define STAGE_BYTES (STAGE_FLOATS * 4)          // 30464
#define SMEM_DYN (2 * STAGE_BYTES)              // 60928 (dynamic shared)

// Output layout (concatenated reference tuple, all fp32):
//   pos [B,1] | shared [B,H] | logits [B,C] | distance [B,P]
#define POS_OFF    ((size_t)0)
#define SHARED_OFF ((size_t)Bsz)
#define LOGITS_OFF (SHARED_OFF + (size_t)Bsz * Hd)
#define DIST_OFF   (LOGITS_OFF + (size_t)Bsz * Cc)

// Single scratch symbol -> ONE memset node per replay.
__device__ float g_scratch[Pp * Hd + Pp];
#define G_UALL   (g_scratch)
#define G_SIMSUM (g_scratch + Pp * Hd)

__device__ __forceinline__ void cpa16(uint32_t dst, const void* src) {
    asm volatile("cp.async.cg.shared.global [%0], [%1], 16;"
                 :: "r"(dst), "l"(src));
}
__device__ __forceinline__ void cpa_commit() {
    asm volatile("cp.async.commit_group;" ::: "memory");
}
__device__ __forceinline__ void cpa_wait1() {
    asm volatile("cp.async.wait_group 1;" ::: "memory");
}

// ---------------------------------------------------------------------------
// K2 fused single launch:
//   blocks [0, DIST_BLOCKS):  tf32 distance GEMM, 64-wide K stages (16 iters,
//                             double-buffered cp.async, 2 barriers/stage)
//   blocks [DIST_BLOCKS, ..): u_all blocks (exact fp32)
// ---------------------------------------------------------------------------
__global__ __launch_bounds__(256, 3) void k2_fused(
    const float* __restrict__ x, const float* __restrict__ protos,
    const float* __restrict__ llw, const float* __restrict__ W,
    float* __restrict__ out) {
    extern __shared__ uint32_t dsmem[];

    const int tid = threadIdx.x;

    // ======================= role: u_all =======================
    if (blockIdx.x >= DIST_BLOCKS) {
        float* psh = (float*)dsmem;             // 48*64 floats = 12 KB
        const int b  = blockIdx.x - DIST_BLOCKS;
        const int j0 = (b & 3) * 256;
        const int i0 = ((b >> 2) & 15) * 64;
        const int ph = b >> 6;                  // proto half: 0 or 1
        for (int idx = tid; idx < 24 * 64; idx += 256) {
            const int p = idx >> 6, i = idx & 63;
            psh[idx] = protos[(size_t)(ph * 24 + p) * Hd + i0 + i];
        }
        __syncthreads();
        const int j = j0 + tid;
        float acc[24];
#pragma unroll
        for (int p = 0; p < 24; p++) acc[p] = 0.f;
        const float* Wp = W + (size_t)i0 * Hd + j;
#pragma unroll 2
        for (int i = 0; i < 64; i += 8) {
            float w[8];
#pragma unroll
            for (int q = 0; q < 8; q++) w[q] = __ldcs(Wp + (size_t)(i + q) * Hd);
#pragma unroll
            for (int p = 0; p < 24; p++) {
                float a = acc[p];
#pragma unroll
                for (int q = 0; q < 8; q++) a = fmaf(w[q], psh[p * 64 + i + q], a);
                acc[p] = a;
            }
        }
#pragma unroll
        for (int p = 0; p < 24; p++)
            atomicAdd(&G_UALL[(ph * 24 + p) * Hd + j], acc[p]);
        return;
    }

    // ======================= role: distance GEMM =======================
    const int lane = tid & 31, warp = tid >> 5;
    const int row0 = blockIdx.x * 64;
    const int g  = lane >> 2;
    const int t4 = lane & 3;

    uint32_t smem0;
    asm("{ .reg .u64 t; cvta.to.shared.u64 t, %1; cvt.u32.u64 %0, t; }"
        : "=r"(smem0) : "l"((void*)dsmem));

    // per-thread cp.async geometry: A = 4 chunks, B = 3 chunks of 16B
    int arow[4], acol[4], brow[3], bcol[3];
    uint32_t adst[4], bdst[3];
    const float* asrc[4];
    const float* bsrc[3];
#pragma unroll
    for (int k = 0; k < 4; k++) {
        const int c = tid + k * 256;            // 0..1023
        arow[k] = c >> 4; acol[k] = c & 15;
        adst[k] = smem0 + (uint32_t)(arow[k] * ROW_STRIDE + acol[k] * 4) * 4;
        asrc[k] = x + (size_t)(row0 + arow[k]) * Hd + acol[k] * 4;
    }
#pragma unroll
    for (int k = 0; k < 3; k++) {
        const int c = tid + k * 256;            // 0..767
        brow[k] = c >> 4; bcol[k] = c & 15;
        bdst[k] = smem0 + (uint32_t)(B_FLOAT_OFF + brow[k] * ROW_STRIDE + bcol[k] * 4) * 4;
        bsrc[k] = protos + (size_t)brow[k] * Hd + bcol[k] * 4;
    }

#define ISSUE_STAGE(S, BUF)                                              \
    do {                                                                 \
        const int _ko = (S) * KSTEP;                                     \
        const uint32_t _b = (uint32_t)(BUF) * STAGE_BYTES;               \
        cpa16(adst[0] + _b, asrc[0] + _ko);                              \
        cpa16(adst[1] + _b, asrc[1] + _ko);                              \
        cpa16(adst[2] + _b, asrc[2] + _ko);                              \
        cpa16(adst[3] + _b, asrc[3] + _ko);                              \
        cpa16(bdst[0] + _b, bsrc[0] + _ko);                              \
        cpa16(bdst[1] + _b, bsrc[1] + _ko);                              \
        cpa16(bdst[2] + _b, bsrc[2] + _ko);                              \
    } while (0)

    ISSUE_STAGE(0, 0); cpa_commit();
    ISSUE_STAGE(1, 1); cpa_commit();

    float acc[3][4];
#pragma unroll
    for (int n = 0; n < 3; n++)
#pragma unroll
        for (int q = 0; q < 4; q++) acc[n][q] = 0.f;
    float sqA = 0.f, sqB = 0.f;
    float pq[3] = {0.f, 0.f, 0.f};

    const int Rg    = (warp & 3) * 16 + g;     // A rows Rg, Rg+8
    const int nhalf = warp >> 2;
    const bool doX2 = (nhalf == 0);
    const bool doP2 = ((warp & 3) == 0);

    for (int s = 0; s < 16; s++) {
        cpa_wait1();
        __syncthreads();

        const uint32_t* xb = dsmem + (s & 1) * STAGE_FLOATS;
        const uint32_t* pb = xb + B_FLOAT_OFF;
#pragma unroll
        for (int kc = 0; kc < KSTEP; kc += 8) {
            const uint32_t a0 = xb[(Rg    ) * ROW_STRIDE + kc + t4];
            const uint32_t a1 = xb[(Rg + 8) * ROW_STRIDE + kc + t4];
            const uint32_t a2 = xb[(Rg    ) * ROW_STRIDE + kc + t4 + 4];
            const uint32_t a3 = xb[(Rg + 8) * ROW_STRIDE + kc + t4 + 4];
            if (doX2) {
                const float f0 = __uint_as_float(a0), f1 = __uint_as_float(a1);
                const float f2 = __uint_as_float(a2), f3 = __uint_as_float(a3);
                sqA = fmaf(f0, f0, sqA); sqA = fmaf(f2, f2, sqA);
                sqB = fmaf(f1, f1, sqB); sqB = fmaf(f3, f3, sqB);
            }
#pragma unroll
            for (int nt = 0; nt < 3; nt++) {
                const int prow = (nhalf * 3 + nt) * 8 + g;
                const uint32_t b0 = pb[prow * ROW_STRIDE + kc + t4];
                const uint32_t b1 = pb[prow * ROW_STRIDE + kc + t4 + 4];
                if (doP2) {
                    const float h0 = __uint_as_float(b0), h1 = __uint_as_float(b1);
                    pq[nt] = fmaf(h0, h0, pq[nt]);
                    pq[nt] = fmaf(h1, h1, pq[nt]);
                }
                asm volatile(
                    "mma.sync.aligned.m16n8k8.row.col.f32.tf32.tf32.f32 "
                    "{%0,%1,%2,%3}, {%4,%5,%6,%7}, {%8,%9}, {%0,%1,%2,%3};"
                    : "+f"(acc[nt][0]), "+f"(acc[nt][1]),
                      "+f"(acc[nt][2]), "+f"(acc[nt][3])
                    : "r"(a0), "r"(a1), "r"(a2), "r"(a3), "r"(b0), "r"(b1));
            }
        }
        __syncthreads();   // everyone done reading buf (s&1)
        if (s + 2 < 16) ISSUE_STAGE(s + 2, s & 1);
        cpa_commit();
    }
    __syncthreads();   // all mma done; safe to alias dsmem as epilogue scratch

    // NOTE: tf32 HMMA truncates fp32 operands in HW (same error class as
    // cvt.rna; validated rel_err ~3.1e-5 since R7).

    // aliased epilogue scratch
    float* ext     = (float*)dsmem;
    float* x2s     = ext;          // 64
    float* p2s     = ext + 64;     // 48
    float* logit_s = ext + 112;    // 128
    float* simPart = ext + 240;    // 48
    float* wks     = ext + 288;    // 96
    for (int i = tid; i < 384; i += 256)
        ext[i] = (i < 288) ? 0.f : llw[i - 288];
    __syncthreads();

    // quad-reduce squared norms (lanes t4=0..3 share a row)
    sqA += __shfl_xor_sync(0xffffffffu, sqA, 1);
    sqA += __shfl_xor_sync(0xffffffffu, sqA, 2);
    sqB += __shfl_xor_sync(0xffffffffu, sqB, 1);
    sqB += __shfl_xor_sync(0xffffffffu, sqB, 2);
    if (doX2 && t4 == 0) {
        atomicAdd(&x2s[Rg],     sqA);
        atomicAdd(&x2s[Rg + 8], sqB);
    }
#pragma unroll
    for (int nt = 0; nt < 3; nt++) {
        pq[nt] += __shfl_xor_sync(0xffffffffu, pq[nt], 1);
        pq[nt] += __shfl_xor_sync(0xffffffffu, pq[nt], 2);
    }
    if (doP2 && t4 == 0) {
#pragma unroll
        for (int nt = 0; nt < 3; nt++)
            atomicAdd(&p2s[(nhalf * 3 + nt) * 8 + g], pq[nt]);
    }
    __syncthreads();

    const int ra = Rg, rb = Rg + 8;
    const float x2a = x2s[ra], x2b = x2s[rb];
    float lgA0 = 0.f, lgA1 = 0.f, lgB0 = 0.f, lgB1 = 0.f;
    float* dd = out + DIST_OFF + (size_t)row0 * 48;
#pragma unroll
    for (int nt = 0; nt < 3; nt++) {
        const int c0 = (nhalf * 3 + nt) * 8 + t4 * 2, c1 = c0 + 1;
        const float dA0 = fmaf(-2.f, acc[nt][0], x2a + p2s[c0]);
        const float dA1 = fmaf(-2.f, acc[nt][1], x2a + p2s[c1]);
        const float dB0 = fmaf(-2.f, acc[nt][2], x2b + p2s[c0]);
        const float dB1 = fmaf(-2.f, acc[nt][3], x2b + p2s[c1]);
        __stcs((float2*)(dd + (size_t)ra * 48 + c0), make_float2(dA0, dA1));
        __stcs((float2*)(dd + (size_t)rb * 48 + c0), make_float2(dB0, dB1));
        const float sA0 = logf((dA0 + 1.f) / (dA0 + EPSf));
        const float sA1 = logf((dA1 + 1.f) / (dA1 + EPSf));
        const float sB0 = logf((dB0 + 1.f) / (dB0 + EPSf));
        const float sB1 = logf((dB1 + 1.f) / (dB1 + EPSf));
        lgA0 = fmaf(sA0, wks[c0], lgA0); lgA0 = fmaf(sA1, wks[c1], lgA0);
        lgA1 = fmaf(sA0, wks[48 + c0], lgA1); lgA1 = fmaf(sA1, wks[48 + c1], lgA1);
        lgB0 = fmaf(sB0, wks[c0], lgB0); lgB0 = fmaf(sB1, wks[c1], lgB0);
        lgB1 = fmaf(sB0, wks[48 + c0], lgB1); lgB1 = fmaf(sB1, wks[48 + c1], lgB1);
        atomicAdd(&simPart[c0], sA0 + sB0);
        atomicAdd(&simPart[c1], sA1 + sB1);
    }
    atomicAdd(&logit_s[ra * 2 + 0], lgA0);
    atomicAdd(&logit_s[ra * 2 + 1], lgA1);
    atomicAdd(&logit_s[rb * 2 + 0], lgB0);
    atomicAdd(&logit_s[rb * 2 + 1], lgB1);
    __syncthreads();

    if (tid < 128) out[LOGITS_OFF + (size_t)row0 * 2 + tid] = logit_s[tid];
    if (tid < 48)  atomicAdd(&G_SIMSUM[tid], simPart[tid]);
#undef ISSUE_STAGE
}

// ---------------------------------------------------------------------------
// K3: in-block argmax -> u[jstar] to smem -> fused shared copy-out + pos dot.
// ---------------------------------------------------------------------------
__global__ __launch_bounds__(512) void k3_pos(
    const float* __restrict__ shr, const float* __restrict__ bb,
    const int* __restrict__ flag, float* __restrict__ out) {
    __shared__ float us[Hd];
    __shared__ int   js_s;
    const int tid = threadIdx.x;

    if (tid < 32) {
        const int idx = (flag[0] != 0) ? 1 : 0;
        float v = (tid < PPCc) ? G_SIMSUM[idx * PPCc + tid] : -INFINITY;
        int bj = tid;
        for (int o = 16; o; o >>= 1) {
            const float ov = __shfl_xor_sync(0xffffffffu, v, o);
            const int   oj = __shfl_xor_sync(0xffffffffu, bj, o);
            if (ov > v || (ov == v && oj < bj)) { v = ov; bj = oj; }
        }
        if (tid == 0) js_s = idx * PPCc + bj;
    }
    __syncthreads();
    const int js = js_s;
    for (int i = tid; i < Hd; i += 512) us[i] = G_UALL[js * Hd + i];
    __syncthreads();

    const int warp = tid >> 5, lane = tid & 31;
    const int r = blockIdx.x * 16 + warp;
    const float4* src = (const float4*)(shr + (size_t)r * Hd);
    float4*       dst = (float4*)(out + SHARED_OFF + (size_t)r * Hd);
    const float4* uf  = (const float4*)us;
    float a0 = 0.f, a1 = 0.f, a2 = 0.f, a3 = 0.f;
#pragma unroll
    for (int t = lane; t < Hd / 4; t += 32) {
        const float4 v = __ldcs(src + t);
        __stcs(dst + t, v);
        const float4 u4 = uf[t];
        a0 = fmaf(v.x, u4.x, a0);
        a1 = fmaf(v.y, u4.y, a1);
        a2 = fmaf(v.z, u4.z, a2);
        a3 = fmaf(v.w, u4.w, a3);
    }
    float acc = (a0 + a1) + (a2 + a3);
    for (int o = 16; o; o >>= 1) acc += __shfl_xor_sync(0xffffffffu, acc, o);
    if (lane == 0) out[POS_OFF + r] = acc + __ldg(bb);
}

// ---------------------------------------------------------------------------
extern "C" void kernel_launch(void* const* d_in, const int* in_sizes, int n_in,
                              void* d_out, int out_size) {
    const float* x      = (const float*)d_in[0];  // specific_user [B,H]
    const float* shr    = (const float*)d_in[1];  // shared_user   [B,H]
    const float* protos = (const float*)d_in[2];  // [P,H]
    const float* llw    = (const float*)d_in[3];  // [C,P]
    const float* W      = (const float*)d_in[4];  // [1,H,H]
    const float* bb     = (const float*)d_in[5];  // [1]
    const int*   flag   = (const int*)d_in[6];    // scalar
    float* out = (float*)d_out;

    // dynamic smem opt-in (host attribute set; idempotent, capture-legal)
    cudaFuncSetAttribute(k2_fused,
                         cudaFuncAttributeMaxDynamicSharedMemorySize, SMEM_DYN);

    // single memset node (uall + simSum live in one symbol)
    void* scr_ptr = nullptr;
    cudaGetSymbolAddress(&scr_ptr, g_scratch);
    cudaMemsetAsync(scr_ptr, 0, (size_t)(Pp * Hd + Pp) * sizeof(float));

    k2_fused<<<DIST_BLOCKS + UALL_BLOCKS, 256, SMEM_DYN>>>(
        x, protos, llw, W, out);
    k3_pos  <<<Bsz / 16, 512>>>(shr, bb, flag, out);
}